// round 16
// baseline (speedup 1.0000x reference)
#include <cuda_runtime.h>
#include <cuda_bf16.h>
#include <math.h>

// Problem constants
#define BB 8
#define TT 2048
#define DIN 256
#define HH 512
#define G4 2048          // 4*H
#define MM (BB*TT)       // 16384
#define NCTA 96          // barrier participants (32 L0 + 64 L1)
#define L0_CTAS 32
#define GEMM_CTAS 52
#define GRID_TOTAL 148

// ---------------- device scratch ----------------
__device__ float g_wx0[(size_t)MM * G4];   // 128 MB: x@W0^T + (w0_b+u0_b)
__device__ float g_h1[2][HH * BB];         // ping-pong h of layer0, layout [j][b]
__device__ float g_h2[2][HH * BB];         // ping-pong h of layer1
__device__ unsigned g_bar;                 // global barrier counter
__device__ unsigned g_chunkcnt[16 * 32];   // per-chunk completion counters (128B stride)

// ---------------- shared memory layout (floats) ----------------
// persist: wS [K][SW] | srcS [K][8] | redS [NKG*R4][36]
// gemm   : As [16][128] | Bs [16][128]
#define OFF_SRC  36864
#define OFF_RED  45056
#define SMEM_FLOATS 54272
#define SMEM_BYTES (SMEM_FLOATS * 4)   // 217088 < 227KB limit

typedef unsigned long long u64;

__device__ __forceinline__ u64 pk2(float x) {
    u64 r; asm("mov.b64 %0, {%1, %1};" : "=l"(r) : "f"(x)); return r;
}
__device__ __forceinline__ void fma2(u64& a, u64 b, u64 c) {
    asm("fma.rn.f32x2 %0, %1, %2, %0;" : "+l"(a) : "l"(b), "l"(c));
}
__device__ __forceinline__ u64 addp(u64 a, u64 b) {
    u64 r; asm("add.rn.f32x2 %0, %1, %2;" : "=l"(r) : "l"(a), "l"(b)); return r;
}
__device__ __forceinline__ void upk(float& lo, float& hi, u64 v) {
    asm("mov.b64 {%0, %1}, %2;" : "=f"(lo), "=f"(hi) : "l"(v));
}
__device__ __forceinline__ float4 ldcg4(const float4* p) { return __ldcg(p); }
__device__ __forceinline__ float fast_sig(float x) {
    return __fdividef(1.f, 1.f + __expf(-x));
}
__device__ __forceinline__ float fast_tanh(float x) {
    float e = __expf(2.f * x);
    return 1.f - __fdividef(2.f, e + 1.f);
}
__device__ __forceinline__ void wait_chunk(int c) {
    const unsigned* p = &g_chunkcnt[c * 32];
    unsigned v;
    do {
        asm volatile("ld.acquire.gpu.global.u32 %0, [%1];" : "=r"(v) : "l"(p) : "memory");
    } while (v < (unsigned)GEMM_CTAS);
}

// 4 packed FMAs: acc[AOFF..AOFF+3] += (w,w) * hpairs
#define FMA_ROW2(AOFF, WV)                                   \
    { u64 wp = pk2(WV);                                      \
      fma2(acc[AOFF+0], wp, hA.x); fma2(acc[AOFF+1], wp, hA.y); \
      fma2(acc[AOFF+2], wp, hB.x); fma2(acc[AOFF+3], wp, hB.y); }

template <int LAYER, int R, int K, int U>
__device__ void run_layer(const float* __restrict__ wA,
                          const float* __restrict__ wB,
                          const float* __restrict__ bA,
                          const float* __restrict__ bB,
                          int ubase, float* sm, float* __restrict__ out)
{
    const int t = threadIdx.x;
    const int lane = t & 31;
    const int w = t >> 5;
    constexpr int R4  = R / 4;       // == U
    constexpr int SW  = R + 4;
    constexpr int NKG = 256 / R4;    // 16 (L0) / 32 (L1)
    constexpr int KCH = K / NKG;     // 32 both
    constexpr int KSH = (K == 512) ? 9 : 10;
    constexpr int TAIL = U * 16;     // 256 (L0) / 128 (L1) tail threads

    float* wS   = sm;
    float* srcS = sm + OFF_SRC;
    float* redS = sm + OFF_RED;

    // ---- one-time weight load (transposed [k][row], padded) ----
    // UNIT-MAJOR row order: local row rr -> unit rr>>2, gate rr&3
    for (int e = t; e < R * K; e += 256) {
        int k  = e & (K - 1);
        int rr = e >> KSH;
        int g  = (rr & 3) * 512 + ubase + (rr >> 2);
        float v;
        if (LAYER == 0) v = wA[g * 512 + k];
        else            v = (k < 512) ? wA[g * 512 + k] : wB[g * 512 + (k - 512)];
        wS[k * SW + rr] = v;
    }

    // tail roles (valid t < TAIL): one gate x one batch-pair each
    const int tu = t >> 4;          // unit
    const int tg = (t >> 2) & 3;    // gate
    const int tp = t & 3;           // batch pair (batches 2tp, 2tp+1)
    const int u64off = 4 * tp + 2 * (tg >> 1) + (tg & 1);

    float biasv1 = 0.f;
    if (LAYER == 1 && t < TAIL)
        biasv1 = bA[tg * 512 + ubase + tu] + bB[tg * 512 + ubase + tu];
    __syncthreads();

    float c0 = 0.f, c1 = 0.f;       // cell state for batches 2tp, 2tp+1 (finalists)
    const int jg = t & (R4 - 1);
    const int kg = t >> ((LAYER == 0) ? 4 : 3);

    // wx prefetch (L0 only)
    float wxv0 = 0.f, wxv1 = 0.f;
    size_t wxo0 = 0, wxo1 = 0;
    if (LAYER == 0 && t < TAIL) {
        wxo0 = ((size_t)((2 * tp) * TT)) * G4 + tg * 512 + ubase + tu;
        wxo1 = ((size_t)((2 * tp + 1) * TT)) * G4 + tg * 512 + ubase + tu;
        wait_chunk(0);
        wxv0 = __ldcg(&g_wx0[wxo0]);
        wxv1 = __ldcg(&g_wx0[wxo1]);
    }

    for (int r = 0; r <= TT; ++r) {
        const bool active = (LAYER == 0) ? (r < TT) : (r >= 1);

        if (active) {
            const int slot = (r + 1) & 1;   // (r-1) mod 2
            // slice-aligned warp-local stage
            float4* dst = (float4*)srcS;
            if (LAYER == 0) {
                const float4* s1 = (const float4*)g_h1[slot];
                const int base = 128 * w + lane;
                dst[base]      = ldcg4(s1 + base);
                dst[base + 32] = ldcg4(s1 + base + 32);
                dst[base + 64] = ldcg4(s1 + base + 64);
                dst[base + 96] = ldcg4(s1 + base + 96);
            } else {
                const float4* s1 = (const float4*)g_h1[slot];
                const float4* s2 = (const float4*)g_h2[slot];
                const float4* src = (w < 4) ? (s1 + 256 * w) : (s2 + 256 * (w - 4));
                float4* d = dst + 256 * w;
                #pragma unroll
                for (int i = 0; i < 8; ++i)
                    d[lane + i * 32] = ldcg4(src + lane + i * 32);
            }
            __syncwarp();

            u64 acc[16];
            #pragma unroll
            for (int i = 0; i < 16; ++i) acc[i] = 0ull;
            const float4* w4 = (const float4*)wS;
            const int kbase = kg * KCH;
            #pragma unroll 8
            for (int kk = 0; kk < KCH; ++kk) {
                const int k = kbase + kk;
                float4 wv = w4[k * (SW / 4) + jg];
                const ulonglong2* hsrc = (const ulonglong2*)(srcS + k * 8);
                ulonglong2 hA = hsrc[0];   // batch pairs (0,1),(2,3)
                ulonglong2 hB = hsrc[1];   // batch pairs (4,5),(6,7)
                FMA_ROW2(0,  wv.x)
                FMA_ROW2(4,  wv.y)
                FMA_ROW2(8,  wv.z)
                FMA_ROW2(12, wv.w)
            }
            // pair-major partial store: u64 index 4p + 2*(g>>1) + (g&1), 8 x STS.128
            ulonglong2* rb = (ulonglong2*)(redS + (kg * R4 + jg) * 36);
            #pragma unroll
            for (int j = 0; j < 8; ++j) {
                const int p = j >> 1, g0 = (j & 1) * 2;
                rb[j] = make_ulonglong2(acc[g0 * 4 + p], acc[(g0 + 1) * 4 + p]);
            }
        }
        __syncthreads();   // redS ready for the merged tail

        float h_def0 = 0.f, h_def1 = 0.f;   // deferred output values (L1 finalists)
        if (active && t < TAIL) {
            // one gate x batch-pair per thread: NKG x LDS.64, packed adds
            u64 sp = 0ull;
            #pragma unroll
            for (int k2 = 0; k2 < NKG; ++k2) {
                const u64* rowp = (const u64*)(redS + (k2 * R4 + tu) * 36);
                sp = addp(sp, rowp[u64off]);
            }
            float v0, v1; upk(v0, v1, sp);
            float s0, s1;
            if (LAYER == 0) { s0 = v0 + wxv0;  s1 = v1 + wxv1;  }
            else            { s0 = v0 + biasv1; s1 = v1 + biasv1; }
            float a0 = (tg == 2) ? fast_tanh(s0) : fast_sig(s0);
            float a1 = (tg == 2) ? fast_tanh(s1) : fast_sig(s1);
            // gather 4 gates of (unit, pair): lanes l0 | {0,4,8,12}
            const unsigned m = 0xffffffffu;
            const int l0 = lane & 0x13;     // clear gate bits [2:3]
            float ff0 = __shfl_sync(m, a0, l0 | 4);
            float ff1 = __shfl_sync(m, a1, l0 | 4);
            float gg0 = __shfl_sync(m, a0, l0 | 8);
            float gg1 = __shfl_sync(m, a1, l0 | 8);
            float oo0 = __shfl_sync(m, a0, l0 | 12);
            float oo1 = __shfl_sync(m, a1, l0 | 12);
            if (tg == 0) {
                c0 = ff0 * c0 + a0 * gg0;
                c1 = ff1 * c1 + a1 * gg1;
                float h0 = oo0 * fmaxf(c0, 0.f);
                float h1 = oo1 * fmaxf(c1, 0.f);
                const int j = ubase + tu;
                const int slotw = r & 1;
                float2 hv = make_float2(h0, h1);
                if (LAYER == 0) {
                    __stcg((float2*)&g_h1[slotw][j * 8 + 2 * tp], hv);
                    if (r == TT - 1) {
                        out[8388608 + (2 * tp) * 512 + j]     = h0;   // hh[0]
                        out[8388608 + (2 * tp + 1) * 512 + j] = h1;
                        out[8396800 + (2 * tp) * 512 + j]     = c0;   // cc[0]
                        out[8396800 + (2 * tp + 1) * 512 + j] = c1;
                    }
                } else {
                    __stcg((float2*)&g_h2[slotw][j * 8 + 2 * tp], hv);
                    h_def0 = h0; h_def1 = h1;
                    if (r == TT) {   // last epoch: no barrier follows, store now
                        out[((size_t)((2 * tp) * TT + (r - 1))) * HH + j]     = h0;
                        out[((size_t)((2 * tp + 1) * TT + (r - 1))) * HH + j] = h1;
                        out[8392704 + (2 * tp) * 512 + j]     = h0;   // hh[1]
                        out[8392704 + (2 * tp + 1) * 512 + j] = h1;
                        out[8400896 + (2 * tp) * 512 + j]     = c0;   // cc[1]
                        out[8400896 + (2 * tp + 1) * 512 + j] = c1;
                    }
                }
            }
        }

        // prefetch next round's wx (lands during the barrier spin);
        // gate at chunk boundaries (once per 128 rounds)
        if (LAYER == 0 && t < TAIL && r + 1 < TT) {
            const int rn = r + 1;
            if ((rn & 127) == 0) wait_chunk(rn >> 7);
            wxv0 = __ldcg(&g_wx0[wxo0 + (size_t)rn * G4]);
            wxv1 = __ldcg(&g_wx0[wxo1 + (size_t)rn * G4]);
        }

        if (r < TT) {
            if (t < TAIL) asm volatile("bar.sync 1, %0;" :: "n"(TAIL) : "memory");
            if (t == 0)
                asm volatile("red.release.gpu.global.add.u32 [%0], 1;"
                             :: "l"(&g_bar) : "memory");
            // deferred output stores: overlap t0's spin
            if (LAYER == 1 && active && t < TAIL && tg == 0) {
                const int j = ubase + tu;
                out[((size_t)((2 * tp) * TT + (r - 1))) * HH + j]     = h_def0;
                out[((size_t)((2 * tp + 1) * TT + (r - 1))) * HH + j] = h_def1;
            }
            if (t == 0) {
                const unsigned target = (unsigned)NCTA * (unsigned)(r + 1);
                unsigned v;
                do {
                    asm volatile("ld.acquire.gpu.global.u32 %0, [%1];"
                                 : "=r"(v) : "l"(&g_bar) : "memory");
                } while (v < target);
            }
            __syncthreads();
        }
    }
}

// ---------------- GEMM worker: wx0 tiles in r-chunk-major order ----------------
__device__ void gemm_worker(const float* __restrict__ X, const float* __restrict__ W,
                            const float* __restrict__ b0, const float* __restrict__ ub0,
                            int g, float* sm)
{
    float* As = sm;          // [16][128]
    float* Bs = sm + 2048;   // [16][128]
    const int t = threadIdx.x;
    const int tm = t & 15, tn = t >> 4;

    for (int c = 0; c < 16; ++c) {
        for (int tile = g; tile < 128; tile += GEMM_CTAS) {
            const int b  = tile >> 4;
            const int bn = tile & 15;
            const int bm = b * 16 + c;

            u64 accp[8][4];
            #pragma unroll
            for (int i = 0; i < 8; ++i)
                #pragma unroll
                for (int j = 0; j < 4; ++j) accp[i][j] = 0ull;

            for (int kt = 0; kt < DIN; kt += 16) {
                #pragma unroll
                for (int i = 0; i < 2; ++i) {
                    int f = t * 2 + i;
                    int row = f >> 2, kq = f & 3;
                    float4 a = *(const float4*)&X[(size_t)(bm * 128 + row) * DIN + kt + kq * 4];
                    As[(kq * 4 + 0) * 128 + row] = a.x;
                    As[(kq * 4 + 1) * 128 + row] = a.y;
                    As[(kq * 4 + 2) * 128 + row] = a.z;
                    As[(kq * 4 + 3) * 128 + row] = a.w;
                    float4 bv = *(const float4*)&W[(size_t)(bn * 128 + row) * DIN + kt + kq * 4];
                    Bs[(kq * 4 + 0) * 128 + row] = bv.x;
                    Bs[(kq * 4 + 1) * 128 + row] = bv.y;
                    Bs[(kq * 4 + 2) * 128 + row] = bv.z;
                    Bs[(kq * 4 + 3) * 128 + row] = bv.w;
                }
                __syncthreads();
                #pragma unroll
                for (int k = 0; k < 16; ++k) {
                    float4 a0 = *(const float4*)&As[k * 128 + tm * 8];
                    float4 a1 = *(const float4*)&As[k * 128 + tm * 8 + 4];
                    const ulonglong2* bp = (const ulonglong2*)&Bs[k * 128 + tn * 8];
                    ulonglong2 c01 = bp[0];
                    ulonglong2 c23 = bp[1];
                    float av[8] = {a0.x, a0.y, a0.z, a0.w, a1.x, a1.y, a1.z, a1.w};
                    #pragma unroll
                    for (int i = 0; i < 8; ++i) {
                        u64 wp = pk2(av[i]);
                        fma2(accp[i][0], wp, c01.x);
                        fma2(accp[i][1], wp, c01.y);
                        fma2(accp[i][2], wp, c23.x);
                        fma2(accp[i][3], wp, c23.y);
                    }
                }
                __syncthreads();
            }

            const int gbase = bn * 128 + tn * 8;
            float bias[8];
            #pragma unroll
            for (int j = 0; j < 8; ++j)
                bias[j] = __ldg(&b0[gbase + j]) + __ldg(&ub0[gbase + j]);
            #pragma unroll
            for (int i = 0; i < 8; ++i) {
                const int m = bm * 128 + tm * 8 + i;
                float v[8];
                #pragma unroll
                for (int p = 0; p < 4; ++p) upk(v[2 * p], v[2 * p + 1], accp[i][p]);
                float4 o0 = make_float4(v[0] + bias[0], v[1] + bias[1],
                                        v[2] + bias[2], v[3] + bias[3]);
                float4 o1 = make_float4(v[4] + bias[4], v[5] + bias[5],
                                        v[6] + bias[6], v[7] + bias[7]);
                *(float4*)&g_wx0[(size_t)m * G4 + gbase]     = o0;
                *(float4*)&g_wx0[(size_t)m * G4 + gbase + 4] = o1;
            }
        }
        // all this CTA's tiles of chunk c done -> arrive
        if (t == 0)
            asm volatile("red.release.gpu.global.add.u32 [%0], 1;"
                         :: "l"(&g_chunkcnt[c * 32]) : "memory");
    }
}

__global__ void __launch_bounds__(256, 1)
lstm_persist(const float* __restrict__ x,
             const float* __restrict__ w0w, const float* __restrict__ w0b,
             const float* __restrict__ u0w, const float* __restrict__ u0b,
             const float* __restrict__ w1w, const float* __restrict__ w1b,
             const float* __restrict__ u1w, const float* __restrict__ u1b,
             float* __restrict__ out)
{
    extern __shared__ float sm[];
    const int cta = blockIdx.x;
    if (cta < L0_CTAS) {
        run_layer<0, 64, 512, 16>(u0w, nullptr, nullptr, nullptr, cta * 16, sm, out);
    } else if (cta < NCTA) {
        run_layer<1, 32, 1024, 8>(w1w, u1w, w1b, u1b, (cta - L0_CTAS) * 8, sm, out);
    } else {
        gemm_worker(x, w0w, w0b, u0b, cta - NCTA, sm);
    }
}

__global__ void init_k() {
    int t = threadIdx.x;
    float* h1f = (float*)g_h1;
    float* h2f = (float*)g_h2;
    for (int i = t; i < 2 * HH * BB; i += 256) { h1f[i] = 0.f; h2f[i] = 0.f; }
    if (t == 0) g_bar = 0u;
    if (t < 16) g_chunkcnt[t * 32] = 0u;
}

extern "C" void kernel_launch(void* const* d_in, const int* in_sizes, int n_in,
                              void* d_out, int out_size)
{
    const float* x    = (const float*)d_in[0];
    const float* w0_w = (const float*)d_in[1];
    const float* w0_b = (const float*)d_in[2];
    const float* u0_w = (const float*)d_in[3];
    const float* u0_b = (const float*)d_in[4];
    const float* w1_w = (const float*)d_in[5];
    const float* w1_b = (const float*)d_in[6];
    const float* u1_w = (const float*)d_in[7];
    const float* u1_b = (const float*)d_in[8];
    float* out = (float*)d_out;

    static int attr_done = 0;
    if (!attr_done) {
        cudaFuncSetAttribute(lstm_persist, cudaFuncAttributeMaxDynamicSharedMemorySize, SMEM_BYTES);
        attr_done = 1;
    }

    init_k<<<1, 256>>>();
    lstm_persist<<<GRID_TOTAL, 256, SMEM_BYTES>>>(x, w0_w, w0_b, u0_w, u0_b,
                                                  w1_w, w1_b, u1_w, u1_b, out);
}

// round 17
// speedup vs baseline: 1.0485x; 1.0485x over previous
#include <cuda_runtime.h>
#include <cuda_bf16.h>
#include <math.h>

// Problem constants
#define BB 8
#define TT 2048
#define DIN 256
#define HH 512
#define G4 2048          // 4*H
#define MM (BB*TT)       // 16384
#define NCTA 96          // barrier participants (32 L0 + 64 L1)
#define L0_CTAS 32
#define GEMM_CTAS 52
#define GRID_TOTAL 148

// ---------------- device scratch ----------------
__device__ float g_wx0[(size_t)MM * G4];   // 128 MB: x@W0^T + (w0_b+u0_b)
__device__ float g_h1[2][HH * BB];         // ping-pong h of layer0, layout [j][b]
__device__ float g_h2[2][HH * BB];         // ping-pong h of layer1
__device__ unsigned g_bar;                 // global barrier counter
__device__ unsigned g_chunkcnt[16 * 32];   // per-chunk completion counters (128B stride)

// ---------------- shared memory layout (floats) ----------------
// persist: wS [K][SW] | srcS [K][8] | redS [NKG*R4][36]
// gemm   : As [16][128] | Bs [16][128]
#define OFF_SRC  36864
#define OFF_RED  45056
#define SMEM_FLOATS 54272
#define SMEM_BYTES (SMEM_FLOATS * 4)   // 217088 < 227KB limit

typedef unsigned long long u64;

__device__ __forceinline__ u64 pk2(float x) {
    u64 r; asm("mov.b64 %0, {%1, %1};" : "=l"(r) : "f"(x)); return r;
}
__device__ __forceinline__ void fma2(u64& a, u64 b, u64 c) {
    asm("fma.rn.f32x2 %0, %1, %2, %0;" : "+l"(a) : "l"(b), "l"(c));
}
__device__ __forceinline__ u64 addp(u64 a, u64 b) {
    u64 r; asm("add.rn.f32x2 %0, %1, %2;" : "=l"(r) : "l"(a), "l"(b)); return r;
}
__device__ __forceinline__ void upk(float& lo, float& hi, u64 v) {
    asm("mov.b64 {%0, %1}, %2;" : "=f"(lo), "=f"(hi) : "l"(v));
}
__device__ __forceinline__ float4 ldcg4(const float4* p) { return __ldcg(p); }
__device__ __forceinline__ float fast_sig(float x) {
    return __fdividef(1.f, 1.f + __expf(-x));
}
__device__ __forceinline__ float fast_tanh(float x) {
    float e = __expf(2.f * x);
    return 1.f - __fdividef(2.f, e + 1.f);
}
__device__ __forceinline__ void wait_chunk(int c) {
    const unsigned* p = &g_chunkcnt[c * 32];
    unsigned v;
    do {
        asm volatile("ld.acquire.gpu.global.u32 %0, [%1];" : "=r"(v) : "l"(p) : "memory");
    } while (v < (unsigned)GEMM_CTAS);
}

// 4 packed FMAs: acc[AOFF..AOFF+3] += (w,w) * hpairs
#define FMA_ROW2(AOFF, WV)                                   \
    { u64 wp = pk2(WV);                                      \
      fma2(acc[AOFF+0], wp, hA.x); fma2(acc[AOFF+1], wp, hA.y); \
      fma2(acc[AOFF+2], wp, hB.x); fma2(acc[AOFF+3], wp, hB.y); }

template <int LAYER, int R, int K, int U>
__device__ void run_layer(const float* __restrict__ wA,
                          const float* __restrict__ wB,
                          const float* __restrict__ bA,
                          const float* __restrict__ bB,
                          int ubase, float* sm, float* __restrict__ out)
{
    const int t = threadIdx.x;
    const int lane = t & 31;
    const int w = t >> 5;
    constexpr int R4  = R / 4;
    constexpr int SW  = R + 4;
    constexpr int NKG = 256 / R4;    // 16 (L0) / 32 (L1)
    constexpr int KCH = K / NKG;     // 32 both
    constexpr int KSH = (K == 512) ? 9 : 10;
    constexpr int UPD = U * 8;       // 128 (L0) / 64 (L1)

    float* wS   = sm;
    float* srcS = sm + OFF_SRC;
    float* redS = sm + OFF_RED;

    // ---- one-time weight load (transposed [k][row], padded) ----
    // UNIT-MAJOR row order: local row rr -> unit rr>>2, gate rr&3
    for (int e = t; e < R * K; e += 256) {
        int k  = e & (K - 1);
        int rr = e >> KSH;
        int g  = (rr & 3) * 512 + ubase + (rr >> 2);
        float v;
        if (LAYER == 0) v = wA[g * 512 + k];
        else            v = (k < 512) ? wA[g * 512 + k] : wB[g * 512 + (k - 512)];
        wS[k * SW + rr] = v;
    }

    const int uu = t >> 3;
    const int ub = t & 7;

    float biasv[4] = {0.f, 0.f, 0.f, 0.f};
    if (LAYER == 1 && t < UPD) {
        #pragma unroll
        for (int g = 0; g < 4; ++g) {
            int gi = g * 512 + ubase + uu;
            biasv[g] = bA[gi] + bB[gi];
        }
    }
    __syncthreads();

    float c_state = 0.f;
    const int jg = t & (R4 - 1);
    const int kg = t >> ((LAYER == 0) ? 4 : 3);

    // wx prefetch (L0 only): wait for chunk 0, then load round 0
    float wxv[4] = {0.f, 0.f, 0.f, 0.f};
    const float* wxrow = (LAYER == 0)
        ? &g_wx0[((size_t)(ub * TT)) * G4 + ubase + uu] : nullptr;
    if (LAYER == 0 && t < UPD) {
        wait_chunk(0);
        #pragma unroll
        for (int g = 0; g < 4; ++g) wxv[g] = __ldcg(wxrow + g * 512);
    }

    for (int r = 0; r <= TT; ++r) {
        const bool active = (LAYER == 0) ? (r < TT) : (r >= 1);

        if (active) {
            const int slot = (r + 1) & 1;   // (r-1) mod 2
            // slice-aligned warp-local stage
            float4* dst = (float4*)srcS;
            if (LAYER == 0) {
                const float4* s1 = (const float4*)g_h1[slot];
                const int base = 128 * w + lane;
                dst[base]      = ldcg4(s1 + base);
                dst[base + 32] = ldcg4(s1 + base + 32);
                dst[base + 64] = ldcg4(s1 + base + 64);
                dst[base + 96] = ldcg4(s1 + base + 96);
            } else {
                const float4* s1 = (const float4*)g_h1[slot];
                const float4* s2 = (const float4*)g_h2[slot];
                const float4* src = (w < 4) ? (s1 + 256 * w) : (s2 + 256 * (w - 4));
                float4* d = dst + 256 * w;
                #pragma unroll
                for (int i = 0; i < 8; ++i)
                    d[lane + i * 32] = ldcg4(src + lane + i * 32);
            }
            __syncwarp();

            u64 acc[16];
            #pragma unroll
            for (int i = 0; i < 16; ++i) acc[i] = 0ull;
            const float4* w4 = (const float4*)wS;
            const int kbase = kg * KCH;
            #pragma unroll 8
            for (int kk = 0; kk < KCH; ++kk) {
                const int k = kbase + kk;
                float4 wv = w4[k * (SW / 4) + jg];
                const ulonglong2* hsrc = (const ulonglong2*)(srcS + k * 8);
                ulonglong2 hA = hsrc[0];   // batch pairs (0,1),(2,3)
                ulonglong2 hB = hsrc[1];   // batch pairs (4,5),(6,7)
                FMA_ROW2(0,  wv.x)
                FMA_ROW2(4,  wv.y)
                FMA_ROW2(8,  wv.z)
                FMA_ROW2(12, wv.w)
            }
            // pair-major partial store: u64 index p*4+g, 8 x STS.128
            ulonglong2* rb = (ulonglong2*)(redS + (kg * R4 + jg) * 36);
            #pragma unroll
            for (int j = 0; j < 8; ++j) {
                const int p = j >> 1, g0 = (j & 1) * 2;
                rb[j] = make_ulonglong2(acc[g0 * 4 + p], acc[(g0 + 1) * 4 + p]);
            }
        }
        __syncthreads();   // redS ready for the merged tail

        float h_def = 0.f;   // deferred output value (L1)
        if (active && t < UPD) {
            // packed tail reduce: 2 x LDS.128 per k-group, dual accumulator
            // sets (even/odd k-groups) -> 8 independent addp chains
            const int p = ub >> 1, hb = ub & 1;
            u64 sa0 = 0ull, sa1 = 0ull, sa2 = 0ull, sa3 = 0ull;
            u64 sb0 = 0ull, sb1 = 0ull, sb2 = 0ull, sb3 = 0ull;
            #pragma unroll
            for (int k2 = 0; k2 < NKG; k2 += 2) {
                const ulonglong2* ra =
                    (const ulonglong2*)(redS + (k2 * R4 + uu) * 36 + p * 8);
                const ulonglong2* rbq =
                    (const ulonglong2*)(redS + ((k2 + 1) * R4 + uu) * 36 + p * 8);
                ulonglong2 va0 = ra[0],  va1 = ra[1];
                ulonglong2 vb0 = rbq[0], vb1 = rbq[1];
                sa0 = addp(sa0, va0.x); sa1 = addp(sa1, va0.y);
                sa2 = addp(sa2, va1.x); sa3 = addp(sa3, va1.y);
                sb0 = addp(sb0, vb0.x); sb1 = addp(sb1, vb0.y);
                sb2 = addp(sb2, vb1.x); sb3 = addp(sb3, vb1.y);
            }
            u64 sp0 = addp(sa0, sb0);
            u64 sp1 = addp(sa1, sb1);
            u64 sp2 = addp(sa2, sb2);
            u64 sp3 = addp(sa3, sb3);
            float s4[4];
            {
                float lo, hi;
                upk(lo, hi, sp0); s4[0] = hb ? hi : lo;
                upk(lo, hi, sp1); s4[1] = hb ? hi : lo;
                upk(lo, hi, sp2); s4[2] = hb ? hi : lo;
                upk(lo, hi, sp3); s4[3] = hb ? hi : lo;
            }
            #pragma unroll
            for (int g = 0; g < 4; ++g)
                s4[g] += (LAYER == 0) ? wxv[g] : biasv[g];

            float si = fast_sig(s4[0]);
            float sf = fast_sig(s4[1]);
            float tg = fast_tanh(s4[2]);
            float so = fast_sig(s4[3]);
            c_state = sf * c_state + si * tg;
            float h = so * fmaxf(c_state, 0.f);
            const int j = ubase + uu;
            const int slotw = r & 1;
            if (LAYER == 0) {
                __stcg(&g_h1[slotw][j * 8 + ub], h);
                if (r == TT - 1) {
                    out[8388608 + ub * 512 + j] = h;        // hh[0]
                    out[8396800 + ub * 512 + j] = c_state;  // cc[0]
                }
            } else {
                __stcg(&g_h2[slotw][j * 8 + ub], h);
                h_def = h;
                if (r == TT) {   // last epoch: no barrier follows, store now
                    out[((size_t)(ub * TT + (r - 1))) * HH + j] = h;
                    out[8388608 + 4096 + ub * 512 + j] = h;        // hh[1]
                    out[8396800 + 4096 + ub * 512 + j] = c_state;  // cc[1]
                }
            }
        }

        // prefetch next round's wx (lands during the barrier spin);
        // gate at chunk boundaries (once per 128 rounds)
        if (LAYER == 0 && t < UPD && r + 1 < TT) {
            const int rn = r + 1;
            if ((rn & 127) == 0) wait_chunk(rn >> 7);
            const float* p2 = wxrow + (size_t)rn * G4;
            #pragma unroll
            for (int g = 0; g < 4; ++g) wxv[g] = __ldcg(p2 + g * 512);
        }

        if (r < TT) {
            if (t < UPD) asm volatile("bar.sync 1, %0;" :: "n"(UPD) : "memory");
            if (t == 0)
                asm volatile("red.release.gpu.global.add.u32 [%0], 1;"
                             :: "l"(&g_bar) : "memory");
            // deferred output store: overlaps t0's spin
            if (LAYER == 1 && active && t < UPD) {
                const int j = ubase + uu;
                out[((size_t)(ub * TT + (r - 1))) * HH + j] = h_def;
            }
            if (t == 0) {
                const unsigned target = (unsigned)NCTA * (unsigned)(r + 1);
                unsigned v;
                do {
                    asm volatile("ld.acquire.gpu.global.u32 %0, [%1];"
                                 : "=r"(v) : "l"(&g_bar) : "memory");
                } while (v < target);
            }
            __syncthreads();
        }
    }
}

// ---------------- GEMM worker: wx0 tiles in r-chunk-major order ----------------
__device__ void gemm_worker(const float* __restrict__ X, const float* __restrict__ W,
                            const float* __restrict__ b0, const float* __restrict__ ub0,
                            int g, float* sm)
{
    float* As = sm;          // [16][128]
    float* Bs = sm + 2048;   // [16][128]
    const int t = threadIdx.x;
    const int tm = t & 15, tn = t >> 4;

    for (int c = 0; c < 16; ++c) {
        for (int tile = g; tile < 128; tile += GEMM_CTAS) {
            const int b  = tile >> 4;
            const int bn = tile & 15;
            const int bm = b * 16 + c;

            u64 accp[8][4];
            #pragma unroll
            for (int i = 0; i < 8; ++i)
                #pragma unroll
                for (int j = 0; j < 4; ++j) accp[i][j] = 0ull;

            for (int kt = 0; kt < DIN; kt += 16) {
                #pragma unroll
                for (int i = 0; i < 2; ++i) {
                    int f = t * 2 + i;
                    int row = f >> 2, kq = f & 3;
                    float4 a = *(const float4*)&X[(size_t)(bm * 128 + row) * DIN + kt + kq * 4];
                    As[(kq * 4 + 0) * 128 + row] = a.x;
                    As[(kq * 4 + 1) * 128 + row] = a.y;
                    As[(kq * 4 + 2) * 128 + row] = a.z;
                    As[(kq * 4 + 3) * 128 + row] = a.w;
                    float4 bv = *(const float4*)&W[(size_t)(bn * 128 + row) * DIN + kt + kq * 4];
                    Bs[(kq * 4 + 0) * 128 + row] = bv.x;
                    Bs[(kq * 4 + 1) * 128 + row] = bv.y;
                    Bs[(kq * 4 + 2) * 128 + row] = bv.z;
                    Bs[(kq * 4 + 3) * 128 + row] = bv.w;
                }
                __syncthreads();
                #pragma unroll
                for (int k = 0; k < 16; ++k) {
                    float4 a0 = *(const float4*)&As[k * 128 + tm * 8];
                    float4 a1 = *(const float4*)&As[k * 128 + tm * 8 + 4];
                    const ulonglong2* bp = (const ulonglong2*)&Bs[k * 128 + tn * 8];
                    ulonglong2 c01 = bp[0];
                    ulonglong2 c23 = bp[1];
                    float av[8] = {a0.x, a0.y, a0.z, a0.w, a1.x, a1.y, a1.z, a1.w};
                    #pragma unroll
                    for (int i = 0; i < 8; ++i) {
                        u64 wp = pk2(av[i]);
                        fma2(accp[i][0], wp, c01.x);
                        fma2(accp[i][1], wp, c01.y);
                        fma2(accp[i][2], wp, c23.x);
                        fma2(accp[i][3], wp, c23.y);
                    }
                }
                __syncthreads();
            }

            const int gbase = bn * 128 + tn * 8;
            float bias[8];
            #pragma unroll
            for (int j = 0; j < 8; ++j)
                bias[j] = __ldg(&b0[gbase + j]) + __ldg(&ub0[gbase + j]);
            #pragma unroll
            for (int i = 0; i < 8; ++i) {
                const int m = bm * 128 + tm * 8 + i;
                float v[8];
                #pragma unroll
                for (int p = 0; p < 4; ++p) upk(v[2 * p], v[2 * p + 1], accp[i][p]);
                float4 o0 = make_float4(v[0] + bias[0], v[1] + bias[1],
                                        v[2] + bias[2], v[3] + bias[3]);
                float4 o1 = make_float4(v[4] + bias[4], v[5] + bias[5],
                                        v[6] + bias[6], v[7] + bias[7]);
                *(float4*)&g_wx0[(size_t)m * G4 + gbase]     = o0;
                *(float4*)&g_wx0[(size_t)m * G4 + gbase + 4] = o1;
            }
        }
        // all this CTA's tiles of chunk c done -> arrive
        if (t == 0)
            asm volatile("red.release.gpu.global.add.u32 [%0], 1;"
                         :: "l"(&g_chunkcnt[c * 32]) : "memory");
    }
}

__global__ void __launch_bounds__(256, 1)
lstm_persist(const float* __restrict__ x,
             const float* __restrict__ w0w, const float* __restrict__ w0b,
             const float* __restrict__ u0w, const float* __restrict__ u0b,
             const float* __restrict__ w1w, const float* __restrict__ w1b,
             const float* __restrict__ u1w, const float* __restrict__ u1b,
             float* __restrict__ out)
{
    extern __shared__ float sm[];
    const int cta = blockIdx.x;
    if (cta < L0_CTAS) {
        run_layer<0, 64, 512, 16>(u0w, nullptr, nullptr, nullptr, cta * 16, sm, out);
    } else if (cta < NCTA) {
        run_layer<1, 32, 1024, 8>(w1w, u1w, w1b, u1b, (cta - L0_CTAS) * 8, sm, out);
    } else {
        gemm_worker(x, w0w, w0b, u0b, cta - NCTA, sm);
    }
}

__global__ void init_k() {
    int t = threadIdx.x;
    float* h1f = (float*)g_h1;
    float* h2f = (float*)g_h2;
    for (int i = t; i < 2 * HH * BB; i += 256) { h1f[i] = 0.f; h2f[i] = 0.f; }
    if (t == 0) g_bar = 0u;
    if (t < 16) g_chunkcnt[t * 32] = 0u;
}

extern "C" void kernel_launch(void* const* d_in, const int* in_sizes, int n_in,
                              void* d_out, int out_size)
{
    const float* x    = (const float*)d_in[0];
    const float* w0_w = (const float*)d_in[1];
    const float* w0_b = (const float*)d_in[2];
    const float* u0_w = (const float*)d_in[3];
    const float* u0_b = (const float*)d_in[4];
    const float* w1_w = (const float*)d_in[5];
    const float* w1_b = (const float*)d_in[6];
    const float* u1_w = (const float*)d_in[7];
    const float* u1_b = (const float*)d_in[8];
    float* out = (float*)d_out;

    static int attr_done = 0;
    if (!attr_done) {
        cudaFuncSetAttribute(lstm_persist, cudaFuncAttributeMaxDynamicSharedMemorySize, SMEM_BYTES);
        attr_done = 1;
    }

    init_k<<<1, 256>>>();
    lstm_persist<<<GRID_TOTAL, 256, SMEM_BYTES>>>(x, w0_w, w0_b, u0_w, u0_b,
                                                  w1_w, w1_b, u1_w, u1_b, out);
}